// round 4
// baseline (speedup 1.0000x reference)
#include <cuda_runtime.h>
#include <cstddef>

// ---------------- problem constants ----------------
#define N_EMB 250000
#define D     128
#define N_IDX 65536

__device__ __constant__ float c_unused; // keep constant bank warm (no-op)

static constexpr float LR  = 1e-3f;
static constexpr float B1  = 0.9f;
static constexpr float B2  = 0.999f;
static constexpr float EPS = 1e-8f;

// ---------------- scratch (static device globals; no allocation in launch) ----
__device__ int   g_counts[N_EMB];
__device__ float g_gsum[(size_t)N_EMB * D];

// ---------------- kernels ----------------

// 1) zero the per-row occurrence counts
__global__ void k_zero_counts() {
    int i = blockIdx.x * blockDim.x + threadIdx.x;
    if (i < N_EMB) g_counts[i] = 0;
}

// 2) histogram of idx occurrences
__global__ void k_count(const int* __restrict__ idx) {
    int i = blockIdx.x * blockDim.x + threadIdx.x;
    if (i < N_IDX) atomicAdd(&g_counts[idx[i]], 1);
}

// 3) zero gsum rows that have duplicates (count > 1).
//    One warp per occurrence; count==1 rows skip (they get a plain store later).
__global__ void k_zero_dup_rows(const int* __restrict__ idx) {
    int w    = (blockIdx.x * blockDim.x + threadIdx.x) >> 5;
    int lane = threadIdx.x & 31;
    if (w >= N_IDX) return;
    int row = idx[w];               // broadcast load within warp
    if (g_counts[row] <= 1) return; // warp-uniform
    float4 z = make_float4(0.f, 0.f, 0.f, 0.f);
    *reinterpret_cast<float4*>(g_gsum + (size_t)row * D + lane * 4) = z;
}

// 4) scatter grads into gsum. Singleton rows: plain vectorized store.
//    Duplicate rows: per-element atomicAdd (rare).
__global__ void k_scatter(const int* __restrict__ idx,
                          const float* __restrict__ grad) {
    int w    = (blockIdx.x * blockDim.x + threadIdx.x) >> 5;
    int lane = threadIdx.x & 31;
    if (w >= N_IDX) return;
    int row = idx[w];
    int c   = g_counts[row];
    float4 g = *reinterpret_cast<const float4*>(grad + (size_t)w * D + lane * 4);
    float* dst = g_gsum + (size_t)row * D + lane * 4;
    if (c == 1) {
        *reinterpret_cast<float4*>(dst) = g;
    } else {
        atomicAdd(dst + 0, g.x);
        atomicAdd(dst + 1, g.y);
        atomicAdd(dst + 2, g.z);
        atomicAdd(dst + 3, g.w);
    }
}

// 5) fused sparse-Adam update + full-table writeback.
//    One warp per row; lane handles 4 consecutive floats (float4).
__device__ __forceinline__ float adam_std(float g, float m, float p,
                                          float c1, float invd2) {
    float mn = B1 * m + (1.0f - B1) * g;
    float pn = B2 * p + (1.0f - B2) * g * g;
    return c1 * mn / (sqrtf(pn * invd2) + EPS);
}

__global__ void __launch_bounds__(256)
k_update(const float* __restrict__ emb,
         const float* __restrict__ step,
         const float* __restrict__ mem,
         const float* __restrict__ pw,
         float*       __restrict__ out) {
    int row  = (blockIdx.x * blockDim.x + threadIdx.x) >> 5;
    int lane = threadIdx.x & 31;
    if (row >= N_EMB) return;

    size_t base = (size_t)row * D + (size_t)lane * 4;
    float4 e = *reinterpret_cast<const float4*>(emb + base);
    int    c = g_counts[row];

    float4 o;
    if (c == 0) {
        // untouched: straight copy
        o = e;
    } else {
        float inv = 1.0f / (float)c;
        float4 g = *reinterpret_cast<const float4*>(g_gsum + base);
        float4 m = *reinterpret_cast<const float4*>(mem + base);
        float4 p = *reinterpret_cast<const float4*>(pw + base);

        float s  = step[row] + 1.0f;
        float d1 = 1.0f - powf(B1, s);
        float d2 = 1.0f - powf(B2, s);
        float c1    = LR / d1;
        float invd2 = 1.0f / d2;

        o.x = e.x - adam_std(g.x * inv, m.x, p.x, c1, invd2);
        o.y = e.y - adam_std(g.y * inv, m.y, p.y, c1, invd2);
        o.z = e.z - adam_std(g.z * inv, m.z, p.z, c1, invd2);
        o.w = e.w - adam_std(g.w * inv, m.w, p.w, c1, invd2);
    }
    *reinterpret_cast<float4*>(out + base) = o;
}

// ---------------- launch ----------------
extern "C" void kernel_launch(void* const* d_in, const int* in_sizes, int n_in,
                              void* d_out, int out_size) {
    const int*   idx   = (const int*)  d_in[0];
    const float* grad  = (const float*)d_in[1];
    const float* emb   = (const float*)d_in[2];
    const float* stepv = (const float*)d_in[3];
    const float* mem   = (const float*)d_in[4];
    const float* pw    = (const float*)d_in[5];
    float* out = (float*)d_out;

    // 1) zero counts
    k_zero_counts<<<(N_EMB + 255) / 256, 256>>>();
    // 2) histogram
    k_count<<<(N_IDX + 255) / 256, 256>>>(idx);
    // 3) zero duplicate rows of gsum (warp per occurrence)
    k_zero_dup_rows<<<(N_IDX * 32) / 256, 256>>>(idx);
    // 4) scatter grads
    k_scatter<<<(N_IDX * 32) / 256, 256>>>(idx, grad);
    // 5) fused Adam + writeback (warp per row)
    long long upd_threads = (long long)N_EMB * 32;
    int upd_blocks = (int)((upd_threads + 255) / 256);
    k_update<<<upd_blocks, 256>>>(emb, stepv, mem, pw, out);
}